// round 1
// baseline (speedup 1.0000x reference)
#include <cuda_runtime.h>

// Scratch (device globals — no allocation allowed).
// g_F: pooled means, layout [bs][512][3], bs = 0..63 -> x side, 64..127 -> y side.
// g_Z: VN-MLP activated output, same layout.
static __device__ float g_F[128 * 512 * 3];
static __device__ float g_Z[128 * 512 * 3];

// ---------------------------------------------------------------------------
// Kernel 1: mean over the point dimension. One block per contiguous row of n
// floats (row index = (b*chan + c)*3 + d). float4 vectorized, warp+smem reduce.
// ---------------------------------------------------------------------------
template <int THREADS>
__global__ void mean_kernel(const float* __restrict__ src, int n4, float inv_n,
                            int chan, int chan_off, int bs_off) {
    __shared__ float sm[8];
    int row = blockIdx.x;
    const float4* p = reinterpret_cast<const float4*>(src) + (long long)row * n4;
    float s = 0.f;
#pragma unroll 4
    for (int i = threadIdx.x; i < n4; i += THREADS) {
        float4 v = __ldg(p + i);
        s += (v.x + v.y) + (v.z + v.w);
    }
#pragma unroll
    for (int off = 16; off > 0; off >>= 1)
        s += __shfl_xor_sync(0xffffffffu, s, off);
    if (THREADS > 32) {
        if ((threadIdx.x & 31) == 0) sm[threadIdx.x >> 5] = s;
        __syncthreads();
        if (threadIdx.x == 0) {
            s = 0.f;
#pragma unroll
            for (int w = 0; w < THREADS / 32; ++w) s += sm[w];
        }
    }
    if (threadIdx.x == 0) {
        int d = row % 3;
        int c = (row / 3) % chan;
        int b = row / (3 * chan);
        g_F[((bs_off + b) * 512 + (chan_off + c)) * 3 + d] = s * inv_n;
    }
}

// ---------------------------------------------------------------------------
// Kernel 2: VN-MLP. For each batch-side bs and output o:
//   p[o,:]  = sum_c W[o,c]     * F[bs,c,:]
//   dv[o,:] = sum_c W_dir[o,c] * F[bs,c,:]
// then VN-LeakyReLU: z = p - ((dot<0) ? 0.8*dot/(d2+eps) : 0) * dv.
// Warp handles 4 outputs x 4 batch-sides; lanes stride the K=512 dim so W
// reads are coalesced; F tile cached in smem (stride-3 -> conflict-free).
// Grid: x = 16 o-tiles (32 outputs each), y = 32 bs-tiles (4 each).
// ---------------------------------------------------------------------------
__global__ void __launch_bounds__(256) vnmlp_kernel(const float* __restrict__ W,
                                                    const float* __restrict__ Wd) {
    __shared__ float Fs[4 * 1536];
    int bs0 = blockIdx.y * 4;
    const float* src = g_F + bs0 * 1536;
    for (int i = threadIdx.x; i < 4 * 1536; i += 256) Fs[i] = src[i];
    __syncthreads();

    int warp = threadIdx.x >> 5, lane = threadIdx.x & 31;
    int o0 = (blockIdx.x * 8 + warp) * 4;

    float acc[4][4][6];
#pragma unroll
    for (int j = 0; j < 4; ++j)
#pragma unroll
        for (int k = 0; k < 4; ++k)
#pragma unroll
            for (int v = 0; v < 6; ++v) acc[j][k][v] = 0.f;

#pragma unroll 2
    for (int step = 0; step < 16; ++step) {
        int c = (step << 5) + lane;
        float w[4], wd[4];
#pragma unroll
        for (int j = 0; j < 4; ++j) {
            w[j]  = __ldg(&W[(o0 + j) * 512 + c]);
            wd[j] = __ldg(&Wd[(o0 + j) * 512 + c]);
        }
#pragma unroll
        for (int k = 0; k < 4; ++k) {
            float f0 = Fs[k * 1536 + c * 3 + 0];
            float f1 = Fs[k * 1536 + c * 3 + 1];
            float f2 = Fs[k * 1536 + c * 3 + 2];
#pragma unroll
            for (int j = 0; j < 4; ++j) {
                acc[j][k][0] = fmaf(w[j],  f0, acc[j][k][0]);
                acc[j][k][1] = fmaf(w[j],  f1, acc[j][k][1]);
                acc[j][k][2] = fmaf(w[j],  f2, acc[j][k][2]);
                acc[j][k][3] = fmaf(wd[j], f0, acc[j][k][3]);
                acc[j][k][4] = fmaf(wd[j], f1, acc[j][k][4]);
                acc[j][k][5] = fmaf(wd[j], f2, acc[j][k][5]);
            }
        }
    }

#pragma unroll
    for (int j = 0; j < 4; ++j)
#pragma unroll
        for (int k = 0; k < 4; ++k)
#pragma unroll
            for (int v = 0; v < 6; ++v) {
                float s = acc[j][k][v];
#pragma unroll
                for (int off = 16; off > 0; off >>= 1)
                    s += __shfl_xor_sync(0xffffffffu, s, off);
                acc[j][k][v] = s;
            }

    if (lane == 0) {
#pragma unroll
        for (int j = 0; j < 4; ++j)
#pragma unroll
            for (int k = 0; k < 4; ++k) {
                float px = acc[j][k][0], py = acc[j][k][1], pz = acc[j][k][2];
                float dx = acc[j][k][3], dy = acc[j][k][4], dz = acc[j][k][5];
                float dot = px * dx + py * dy + pz * dz;
                float d2  = dx * dx + dy * dy + dz * dz;
                float coef = (dot >= 0.f) ? 0.f : 0.8f * dot / (d2 + 1e-6f);
                float* o = g_Z + ((bs0 + k) * 512 + (o0 + j)) * 3;
                o[0] = px - coef * dx;
                o[1] = py - coef * dy;
                o[2] = pz - coef * dz;
            }
    }
}

// ---------------------------------------------------------------------------
// Kernel 3: per-batch Kabsch. cov[d,e] = sum_c xc[c,d]*yc[c,e] accumulated in
// fp64; R = U*Vt replaced by the orthogonal polar factor of cov, computed with
// Higham's Frobenius-scaled Newton iteration (identical result, no SVD).
// One block per batch, 128 threads for the channel reduction.
// ---------------------------------------------------------------------------
__global__ void kabsch_kernel(const float* __restrict__ mu_x,
                              const float* __restrict__ mu_y,
                              float* __restrict__ out) {
    __shared__ double smr[4][11];
    int b = blockIdx.x;
    int tid = threadIdx.x;
    float mx0 = mu_x[b * 3 + 0], mx1 = mu_x[b * 3 + 1], mx2 = mu_x[b * 3 + 2];
    float my0 = mu_y[b * 3 + 0], my1 = mu_y[b * 3 + 1], my2 = mu_y[b * 3 + 2];
    const float* zx = g_Z + b * 1536;
    const float* zy = g_Z + (64 + b) * 1536;

    double a[11];
#pragma unroll
    for (int i = 0; i < 11; ++i) a[i] = 0.0;

    for (int c = tid; c < 512; c += 128) {
        float x0 = zx[c * 3 + 0] - mx0, x1 = zx[c * 3 + 1] - mx1, x2 = zx[c * 3 + 2] - mx2;
        float y0 = zy[c * 3 + 0] - my0, y1 = zy[c * 3 + 1] - my1, y2 = zy[c * 3 + 2] - my2;
        a[0] += (double)x0 * y0; a[1] += (double)x0 * y1; a[2] += (double)x0 * y2;
        a[3] += (double)x1 * y0; a[4] += (double)x1 * y1; a[5] += (double)x1 * y2;
        a[6] += (double)x2 * y0; a[7] += (double)x2 * y1; a[8] += (double)x2 * y2;
        a[9]  += (double)x0 * x0 + (double)x1 * x1 + (double)x2 * x2;
        a[10] += (double)y0 * y0 + (double)y1 * y1 + (double)y2 * y2;
    }
#pragma unroll
    for (int i = 0; i < 11; ++i)
        for (int off = 16; off > 0; off >>= 1)
            a[i] += __shfl_xor_sync(0xffffffffu, a[i], off);
    int warp = tid >> 5, lane = tid & 31;
    if (lane == 0)
        for (int i = 0; i < 11; ++i) smr[warp][i] = a[i];
    __syncthreads();

    if (tid == 0) {
        for (int i = 0; i < 11; ++i)
            a[i] = smr[0][i] + smr[1][i] + smr[2][i] + smr[3][i];
        double X[9];
        for (int i = 0; i < 9; ++i) X[i] = a[i];

        // Scaled Newton polar iteration: X <- 0.5*(mu*X + (1/mu)*X^{-T})
        for (int it = 0; it < 14; ++it) {
            double C[9];
            C[0] = X[4] * X[8] - X[5] * X[7];
            C[1] = X[5] * X[6] - X[3] * X[8];
            C[2] = X[3] * X[7] - X[4] * X[6];
            C[3] = X[2] * X[7] - X[1] * X[8];
            C[4] = X[0] * X[8] - X[2] * X[6];
            C[5] = X[1] * X[6] - X[0] * X[7];
            C[6] = X[1] * X[5] - X[2] * X[4];
            C[7] = X[2] * X[3] - X[0] * X[5];
            C[8] = X[0] * X[4] - X[1] * X[3];
            double det = X[0] * C[0] + X[1] * C[1] + X[2] * C[2];
            double invdet = 1.0 / det;
            double fx2 = 0.0, fc2 = 0.0;
            for (int i = 0; i < 9; ++i) { fx2 += X[i] * X[i]; fc2 += C[i] * C[i]; }
            double fy2 = fc2 * invdet * invdet;            // ||X^{-1}||_F^2
            double mu = sqrt(sqrt(fy2 / fx2));             // (.)^{1/4}
            double inv_mu = 1.0 / mu;
            for (int i = 0; i < 9; ++i)
                X[i] = 0.5 * (mu * X[i] + inv_mu * C[i] * invdet);
        }

        for (int i = 0; i < 9; ++i) out[b * 9 + i] = (float)X[i];
        double t0 = (double)my0 - (X[0] * mx0 + X[1] * mx1 + X[2] * mx2);
        double t1 = (double)my1 - (X[3] * mx0 + X[4] * mx1 + X[5] * mx2);
        double t2 = (double)my2 - (X[6] * mx0 + X[7] * mx1 + X[8] * mx2);
        out[576 + b * 3 + 0] = (float)t0;
        out[576 + b * 3 + 1] = (float)t1;
        out[576 + b * 3 + 2] = (float)t2;
        double xn = sqrt(a[9]), yn = sqrt(a[10]);
        out[768 + b] = (float)(yn / (xn + 1e-6));
    }
}

// ---------------------------------------------------------------------------
extern "C" void kernel_launch(void* const* d_in, const int* in_sizes, int n_in,
                              void* d_out, int out_size) {
    // Input order can be either reference-signature (x0..x3,y0..y3,...) or
    // setup_inputs dict order (x0,y0,x1,y1,...). Disambiguate via sizes:
    // x0 and y0 have identical element counts; x0 vs x1 do not.
    int xi[4], yi[4];
    if (in_sizes[0] == in_sizes[1]) {
        for (int i = 0; i < 4; ++i) { xi[i] = 2 * i; yi[i] = 2 * i + 1; }
    } else {
        for (int i = 0; i < 4; ++i) { xi[i] = i; yi[i] = 4 + i; }
    }
    const float* mu_x = (const float*)d_in[8];
    const float* mu_y = (const float*)d_in[9];
    const float* W    = (const float*)d_in[10];
    const float* Wd   = (const float*)d_in[11];

    static const int chans[4] = {64, 128, 128, 192};
    static const int npts[4]  = {4096, 1024, 256, 64};
    static const int choff[4] = {0, 64, 192, 320};

    for (int i = 0; i < 4; ++i) {
        int rows = 64 * chans[i] * 3;
        int n = npts[i];
        int n4 = n >> 2;
        float inv_n = 1.0f / (float)n;
        const float* sx = (const float*)d_in[xi[i]];
        const float* sy = (const float*)d_in[yi[i]];
        if (n >= 1024) {
            mean_kernel<256><<<rows, 256>>>(sx, n4, inv_n, chans[i], choff[i], 0);
            mean_kernel<256><<<rows, 256>>>(sy, n4, inv_n, chans[i], choff[i], 64);
        } else if (n >= 256) {
            mean_kernel<64><<<rows, 64>>>(sx, n4, inv_n, chans[i], choff[i], 0);
            mean_kernel<64><<<rows, 64>>>(sy, n4, inv_n, chans[i], choff[i], 64);
        } else {
            mean_kernel<32><<<rows, 32>>>(sx, n4, inv_n, chans[i], choff[i], 0);
            mean_kernel<32><<<rows, 32>>>(sy, n4, inv_n, chans[i], choff[i], 64);
        }
    }

    vnmlp_kernel<<<dim3(16, 32), 256>>>(W, Wd);
    kabsch_kernel<<<64, 128>>>(mu_x, mu_y, (float*)d_out);
}

// round 2
// speedup vs baseline: 1.4282x; 1.4282x over previous
#include <cuda_runtime.h>

// Scratch (device globals — no allocation allowed).
// g_F: pooled means, layout [bs][512][3], bs = 0..63 -> x side, 64..127 -> y side.
// g_Z: VN-MLP activated output, same layout.
static __device__ float g_F[128 * 512 * 3];
static __device__ float g_Z[128 * 512 * 3];

// ---------------------------------------------------------------------------
// Kernel 1 (fused): mean over the point dimension for ALL 8 tensors in one
// launch. One warp per row (row = (b*chan + c)*3 + d, contiguous n floats);
// for n=64 a warp covers 2 rows (16 lanes each). Warp-shuffle reduce only —
// no smem, no __syncthreads. __ldcs streaming loads (single-touch data).
// ---------------------------------------------------------------------------
struct MeanArgs {
    const float* src[8];
    int   n4[8];         // floats/4 per row
    float inv_n[8];
    int   chan[8];
    int   chan_off[8];
    int   bs_off[8];
    int   warp_base[9];  // prefix sum of warps per tensor
};

__global__ void __launch_bounds__(256) mean_fused_kernel(MeanArgs A) {
    int w = blockIdx.x * 8 + (threadIdx.x >> 5);
    int lane = threadIdx.x & 31;
    if (w >= A.warp_base[8]) return;

    int t = 0;
#pragma unroll
    for (int i = 1; i < 8; ++i) t += (w >= A.warp_base[i]) ? 1 : 0;
    int lw = w - A.warp_base[t];
    int n4 = A.n4[t];
    const float4* p = reinterpret_cast<const float4*>(A.src[t]);

    int row;
    float s = 0.f;
    bool writer;

    if (n4 >= 32) {
        row = lw;
        const float4* q = p + (long long)row * n4;
#pragma unroll 8
        for (int i = lane; i < n4; i += 32) {
            float4 v = __ldcs(q + i);
            s += (v.x + v.y) + (v.z + v.w);
        }
#pragma unroll
        for (int off = 16; off > 0; off >>= 1)
            s += __shfl_xor_sync(0xffffffffu, s, off);
        writer = (lane == 0);
    } else {
        // n4 == 16 (n = 64): two rows per warp, 16 lanes each.
        row = lw * 2 + (lane >> 4);
        int sl = lane & 15;
        float4 v = __ldcs(p + (long long)row * 16 + sl);
        s = (v.x + v.y) + (v.z + v.w);
#pragma unroll
        for (int off = 8; off > 0; off >>= 1)
            s += __shfl_xor_sync(0xffffffffu, s, off);
        writer = (sl == 0);
    }

    if (writer) {
        int chan = A.chan[t];
        int d = row % 3;
        int c = (row / 3) % chan;
        int b = row / (3 * chan);
        g_F[((A.bs_off[t] + b) * 512 + (A.chan_off[t] + c)) * 3 + d] = s * A.inv_n[t];
    }
}

// ---------------------------------------------------------------------------
// Kernel 2: VN-MLP. For each batch-side bs and output o:
//   p[o,:]  = sum_c W[o,c]     * F[bs,c,:]
//   dv[o,:] = sum_c W_dir[o,c] * F[bs,c,:]
// then VN-LeakyReLU: z = p - ((dot<0) ? 0.8*dot/(d2+eps) : 0) * dv.
// Warp handles 4 outputs x 4 batch-sides; lanes stride the K=512 dim so W
// reads are coalesced; F tile cached in smem (stride-3 -> conflict-free).
// Grid: x = 16 o-tiles (32 outputs each), y = 32 bs-tiles (4 each).
// ---------------------------------------------------------------------------
__global__ void __launch_bounds__(256) vnmlp_kernel(const float* __restrict__ W,
                                                    const float* __restrict__ Wd) {
    __shared__ float Fs[4 * 1536];
    int bs0 = blockIdx.y * 4;
    const float* src = g_F + bs0 * 1536;
    for (int i = threadIdx.x; i < 4 * 1536; i += 256) Fs[i] = src[i];
    __syncthreads();

    int warp = threadIdx.x >> 5, lane = threadIdx.x & 31;
    int o0 = (blockIdx.x * 8 + warp) * 4;

    float acc[4][4][6];
#pragma unroll
    for (int j = 0; j < 4; ++j)
#pragma unroll
        for (int k = 0; k < 4; ++k)
#pragma unroll
            for (int v = 0; v < 6; ++v) acc[j][k][v] = 0.f;

#pragma unroll 2
    for (int step = 0; step < 16; ++step) {
        int c = (step << 5) + lane;
        float w[4], wd[4];
#pragma unroll
        for (int j = 0; j < 4; ++j) {
            w[j]  = __ldg(&W[(o0 + j) * 512 + c]);
            wd[j] = __ldg(&Wd[(o0 + j) * 512 + c]);
        }
#pragma unroll
        for (int k = 0; k < 4; ++k) {
            float f0 = Fs[k * 1536 + c * 3 + 0];
            float f1 = Fs[k * 1536 + c * 3 + 1];
            float f2 = Fs[k * 1536 + c * 3 + 2];
#pragma unroll
            for (int j = 0; j < 4; ++j) {
                acc[j][k][0] = fmaf(w[j],  f0, acc[j][k][0]);
                acc[j][k][1] = fmaf(w[j],  f1, acc[j][k][1]);
                acc[j][k][2] = fmaf(w[j],  f2, acc[j][k][2]);
                acc[j][k][3] = fmaf(wd[j], f0, acc[j][k][3]);
                acc[j][k][4] = fmaf(wd[j], f1, acc[j][k][4]);
                acc[j][k][5] = fmaf(wd[j], f2, acc[j][k][5]);
            }
        }
    }

#pragma unroll
    for (int j = 0; j < 4; ++j)
#pragma unroll
        for (int k = 0; k < 4; ++k)
#pragma unroll
            for (int v = 0; v < 6; ++v) {
                float s = acc[j][k][v];
#pragma unroll
                for (int off = 16; off > 0; off >>= 1)
                    s += __shfl_xor_sync(0xffffffffu, s, off);
                acc[j][k][v] = s;
            }

    if (lane == 0) {
#pragma unroll
        for (int j = 0; j < 4; ++j)
#pragma unroll
            for (int k = 0; k < 4; ++k) {
                float px = acc[j][k][0], py = acc[j][k][1], pz = acc[j][k][2];
                float dx = acc[j][k][3], dy = acc[j][k][4], dz = acc[j][k][5];
                float dot = px * dx + py * dy + pz * dz;
                float d2  = dx * dx + dy * dy + dz * dz;
                float coef = (dot >= 0.f) ? 0.f : 0.8f * dot / (d2 + 1e-6f);
                float* o = g_Z + ((bs0 + k) * 512 + (o0 + j)) * 3;
                o[0] = px - coef * dx;
                o[1] = py - coef * dy;
                o[2] = pz - coef * dz;
            }
    }
}

// ---------------------------------------------------------------------------
// Kernel 3: per-batch Kabsch. cov accumulated in fp64; R = polar factor of
// cov via Higham's Frobenius-scaled Newton iteration (== U*Vt from SVD).
// One block per batch, 128 threads for the channel reduction.
// ---------------------------------------------------------------------------
__global__ void kabsch_kernel(const float* __restrict__ mu_x,
                              const float* __restrict__ mu_y,
                              float* __restrict__ out) {
    __shared__ double smr[4][11];
    int b = blockIdx.x;
    int tid = threadIdx.x;
    float mx0 = mu_x[b * 3 + 0], mx1 = mu_x[b * 3 + 1], mx2 = mu_x[b * 3 + 2];
    float my0 = mu_y[b * 3 + 0], my1 = mu_y[b * 3 + 1], my2 = mu_y[b * 3 + 2];
    const float* zx = g_Z + b * 1536;
    const float* zy = g_Z + (64 + b) * 1536;

    double a[11];
#pragma unroll
    for (int i = 0; i < 11; ++i) a[i] = 0.0;

    for (int c = tid; c < 512; c += 128) {
        float x0 = zx[c * 3 + 0] - mx0, x1 = zx[c * 3 + 1] - mx1, x2 = zx[c * 3 + 2] - mx2;
        float y0 = zy[c * 3 + 0] - my0, y1 = zy[c * 3 + 1] - my1, y2 = zy[c * 3 + 2] - my2;
        a[0] += (double)x0 * y0; a[1] += (double)x0 * y1; a[2] += (double)x0 * y2;
        a[3] += (double)x1 * y0; a[4] += (double)x1 * y1; a[5] += (double)x1 * y2;
        a[6] += (double)x2 * y0; a[7] += (double)x2 * y1; a[8] += (double)x2 * y2;
        a[9]  += (double)x0 * x0 + (double)x1 * x1 + (double)x2 * x2;
        a[10] += (double)y0 * y0 + (double)y1 * y1 + (double)y2 * y2;
    }
#pragma unroll
    for (int i = 0; i < 11; ++i)
        for (int off = 16; off > 0; off >>= 1)
            a[i] += __shfl_xor_sync(0xffffffffu, a[i], off);
    int warp = tid >> 5, lane = tid & 31;
    if (lane == 0)
        for (int i = 0; i < 11; ++i) smr[warp][i] = a[i];
    __syncthreads();

    if (tid == 0) {
        for (int i = 0; i < 11; ++i)
            a[i] = smr[0][i] + smr[1][i] + smr[2][i] + smr[3][i];
        double X[9];
        for (int i = 0; i < 9; ++i) X[i] = a[i];

        // Scaled Newton polar iteration: X <- 0.5*(mu*X + (1/mu)*X^{-T})
        for (int it = 0; it < 14; ++it) {
            double C[9];
            C[0] = X[4] * X[8] - X[5] * X[7];
            C[1] = X[5] * X[6] - X[3] * X[8];
            C[2] = X[3] * X[7] - X[4] * X[6];
            C[3] = X[2] * X[7] - X[1] * X[8];
            C[4] = X[0] * X[8] - X[2] * X[6];
            C[5] = X[1] * X[6] - X[0] * X[7];
            C[6] = X[1] * X[5] - X[2] * X[4];
            C[7] = X[2] * X[3] - X[0] * X[5];
            C[8] = X[0] * X[4] - X[1] * X[3];
            double det = X[0] * C[0] + X[1] * C[1] + X[2] * C[2];
            double invdet = 1.0 / det;
            double fx2 = 0.0, fc2 = 0.0;
            for (int i = 0; i < 9; ++i) { fx2 += X[i] * X[i]; fc2 += C[i] * C[i]; }
            double fy2 = fc2 * invdet * invdet;            // ||X^{-1}||_F^2
            double mu = sqrt(sqrt(fy2 / fx2));             // (.)^{1/4}
            double inv_mu = 1.0 / mu;
            for (int i = 0; i < 9; ++i)
                X[i] = 0.5 * (mu * X[i] + inv_mu * C[i] * invdet);
        }

        for (int i = 0; i < 9; ++i) out[b * 9 + i] = (float)X[i];
        double t0 = (double)my0 - (X[0] * mx0 + X[1] * mx1 + X[2] * mx2);
        double t1 = (double)my1 - (X[3] * mx0 + X[4] * mx1 + X[5] * mx2);
        double t2 = (double)my2 - (X[6] * mx0 + X[7] * mx1 + X[8] * mx2);
        out[576 + b * 3 + 0] = (float)t0;
        out[576 + b * 3 + 1] = (float)t1;
        out[576 + b * 3 + 2] = (float)t2;
        double xn = sqrt(a[9]), yn = sqrt(a[10]);
        out[768 + b] = (float)(yn / (xn + 1e-6));
    }
}

// ---------------------------------------------------------------------------
extern "C" void kernel_launch(void* const* d_in, const int* in_sizes, int n_in,
                              void* d_out, int out_size) {
    // Input order can be either reference-signature (x0..x3,y0..y3,...) or
    // setup_inputs dict order (x0,y0,x1,y1,...). Disambiguate via sizes.
    int xi[4], yi[4];
    if (in_sizes[0] == in_sizes[1]) {
        for (int i = 0; i < 4; ++i) { xi[i] = 2 * i; yi[i] = 2 * i + 1; }
    } else {
        for (int i = 0; i < 4; ++i) { xi[i] = i; yi[i] = 4 + i; }
    }
    const float* mu_x = (const float*)d_in[8];
    const float* mu_y = (const float*)d_in[9];
    const float* W    = (const float*)d_in[10];
    const float* Wd   = (const float*)d_in[11];

    static const int chans[4] = {64, 128, 128, 192};
    static const int npts[4]  = {4096, 1024, 256, 64};
    static const int choff[4] = {0, 64, 192, 320};

    MeanArgs A;
    int wb = 0;
    for (int i = 0; i < 4; ++i) {
        for (int side = 0; side < 2; ++side) {
            int t = i * 2 + side;
            A.src[t]      = (const float*)d_in[side == 0 ? xi[i] : yi[i]];
            A.n4[t]       = npts[i] >> 2;
            A.inv_n[t]    = 1.0f / (float)npts[i];
            A.chan[t]     = chans[i];
            A.chan_off[t] = choff[i];
            A.bs_off[t]   = side == 0 ? 0 : 64;
            A.warp_base[t] = wb;
            int rows = 64 * chans[i] * 3;
            wb += (npts[i] == 64) ? rows / 2 : rows;   // 2 rows/warp when n=64
        }
    }
    A.warp_base[8] = wb;

    int blocks = (wb + 7) / 8;
    mean_fused_kernel<<<blocks, 256>>>(A);
    vnmlp_kernel<<<dim3(16, 32), 256>>>(W, Wd);
    kabsch_kernel<<<64, 128>>>(mu_x, mu_y, (float*)d_out);
}

// round 3
// speedup vs baseline: 1.5508x; 1.0859x over previous
#include <cuda_runtime.h>

// Scratch (device globals — no allocation allowed).
// g_F: pooled means, layout [bs][512][3], bs 0..63 = x side, 64..127 = y side.
// g_Z: VN-MLP activated output, layout [bs][512][3].
static __device__ float g_F[128 * 512 * 3];
static __device__ float g_Z[128 * 512 * 3];

// ---------------------------------------------------------------------------
// Kernel 1 (fused): mean over point dim for ALL 8 tensors in one launch.
// One warp per row; n=64 rows pack 2 per warp. Shuffle-only reduce, __ldcs.
// ---------------------------------------------------------------------------
struct MeanArgs {
    const float* src[8];
    int   n4[8];
    float inv_n[8];
    int   chan[8];
    int   chan_off[8];
    int   bs_off[8];
    int   warp_base[9];
};

__global__ void __launch_bounds__(256) mean_fused_kernel(MeanArgs A) {
    int w = blockIdx.x * 8 + (threadIdx.x >> 5);
    int lane = threadIdx.x & 31;
    if (w >= A.warp_base[8]) return;

    int t = 0;
#pragma unroll
    for (int i = 1; i < 8; ++i) t += (w >= A.warp_base[i]) ? 1 : 0;
    int lw = w - A.warp_base[t];
    int n4 = A.n4[t];
    const float4* p = reinterpret_cast<const float4*>(A.src[t]);

    int row;
    float s = 0.f;
    bool writer;

    if (n4 >= 32) {
        row = lw;
        const float4* q = p + (long long)row * n4;
#pragma unroll 8
        for (int i = lane; i < n4; i += 32) {
            float4 v = __ldcs(q + i);
            s += (v.x + v.y) + (v.z + v.w);
        }
#pragma unroll
        for (int off = 16; off > 0; off >>= 1)
            s += __shfl_xor_sync(0xffffffffu, s, off);
        writer = (lane == 0);
    } else {
        row = lw * 2 + (lane >> 4);
        int sl = lane & 15;
        float4 v = __ldcs(p + (long long)row * 16 + sl);
        s = (v.x + v.y) + (v.z + v.w);
#pragma unroll
        for (int off = 8; off > 0; off >>= 1)
            s += __shfl_xor_sync(0xffffffffu, s, off);
        writer = (sl == 0);
    }

    if (writer) {
        int chan = A.chan[t];
        int d = row % 3;
        int c = (row / 3) % chan;
        int b = row / (3 * chan);
        g_F[((A.bs_off[t] + b) * 512 + (A.chan_off[t] + c)) * 3 + d] = s * A.inv_n[t];
    }
}

// ---------------------------------------------------------------------------
// Kernel 2: VN-MLP with packed f32x2 FMAs.
// Block: 256 thr; grid (16 o-tiles of 32, 16 bs-tiles of 8).
// F tile staged transposed in smem: Fs[bs][dim][512] -> conflict-free LDS.128.
// Warp: 4 outputs, lanes split K (c = step*128 + lane*4, float4 loads of W).
// acc kept as f32x2 pairs over K-halves; horizontal add at the end.
// ---------------------------------------------------------------------------
union F4U { float4 f4; unsigned long long u[2]; float f[4]; };

__device__ __forceinline__ void ffma2(unsigned long long& d,
                                      unsigned long long a, unsigned long long b) {
    asm("fma.rn.f32x2 %0, %1, %2, %0;" : "+l"(d) : "l"(a), "l"(b));
}

__global__ void __launch_bounds__(256) vnmlp_kernel(const float* __restrict__ W,
                                                    const float* __restrict__ Wd) {
    __shared__ float Fs[8 * 1536];   // [bs][dim][512]
    int bs0 = blockIdx.y * 8;
    const float* src = g_F + bs0 * 1536;
    for (int i = threadIdx.x; i < 8 * 1536; i += 256) {
        int bs = i / 1536, r = i % 1536;
        Fs[bs * 1536 + (r % 3) * 512 + (r / 3)] = src[i];
    }
    __syncthreads();

    int warp = threadIdx.x >> 5, lane = threadIdx.x & 31;
    int o0 = blockIdx.x * 32 + warp * 4;

    for (int bs = 0; bs < 8; ++bs) {
        unsigned long long acc[4][6];
#pragma unroll
        for (int j = 0; j < 4; ++j)
#pragma unroll
            for (int v = 0; v < 6; ++v) acc[j][v] = 0ull;

        const float* Fb = Fs + bs * 1536;
#pragma unroll
        for (int step = 0; step < 4; ++step) {
            int idx = step * 32 + lane;
            F4U f0, f1, f2;
            f0.f4 = reinterpret_cast<const float4*>(Fb)[idx];
            f1.f4 = reinterpret_cast<const float4*>(Fb + 512)[idx];
            f2.f4 = reinterpret_cast<const float4*>(Fb + 1024)[idx];
#pragma unroll
            for (int j = 0; j < 4; ++j) {
                F4U w, wd;
                w.f4  = __ldg(reinterpret_cast<const float4*>(W  + (o0 + j) * 512) + idx);
                wd.f4 = __ldg(reinterpret_cast<const float4*>(Wd + (o0 + j) * 512) + idx);
#pragma unroll
                for (int h = 0; h < 2; ++h) {
                    ffma2(acc[j][0], w.u[h],  f0.u[h]);
                    ffma2(acc[j][1], w.u[h],  f1.u[h]);
                    ffma2(acc[j][2], w.u[h],  f2.u[h]);
                    ffma2(acc[j][3], wd.u[h], f0.u[h]);
                    ffma2(acc[j][4], wd.u[h], f1.u[h]);
                    ffma2(acc[j][5], wd.u[h], f2.u[h]);
                }
            }
        }

        float r[4][6];
#pragma unroll
        for (int j = 0; j < 4; ++j)
#pragma unroll
            for (int v = 0; v < 6; ++v) {
                unsigned int lo = (unsigned int)(acc[j][v] & 0xffffffffull);
                unsigned int hi = (unsigned int)(acc[j][v] >> 32);
                float s = __uint_as_float(lo) + __uint_as_float(hi);
#pragma unroll
                for (int off = 16; off > 0; off >>= 1)
                    s += __shfl_xor_sync(0xffffffffu, s, off);
                r[j][v] = s;
            }

        if (lane == 0) {
#pragma unroll
            for (int j = 0; j < 4; ++j) {
                float px = r[j][0], py = r[j][1], pz = r[j][2];
                float dx = r[j][3], dy = r[j][4], dz = r[j][5];
                float dot = px * dx + py * dy + pz * dz;
                float d2  = dx * dx + dy * dy + dz * dz;
                float coef = (dot >= 0.f) ? 0.f : 0.8f * dot / (d2 + 1e-6f);
                float* o = g_Z + ((bs0 + bs) * 512 + (o0 + j)) * 3;
                o[0] = px - coef * dx;
                o[1] = py - coef * dy;
                o[2] = pz - coef * dz;
            }
        }
    }
}

// ---------------------------------------------------------------------------
// Kernel 3: per-batch Kabsch. fp64 cov; polar factor via Newton iteration
// (4 Frobenius-scaled + 5 unscaled). Tree-shaped sums to cut DFMA chains.
// ---------------------------------------------------------------------------
__global__ void kabsch_kernel(const float* __restrict__ mu_x,
                              const float* __restrict__ mu_y,
                              float* __restrict__ out) {
    __shared__ double smr[4][11];
    int b = blockIdx.x;
    int tid = threadIdx.x;
    float mx0 = mu_x[b * 3 + 0], mx1 = mu_x[b * 3 + 1], mx2 = mu_x[b * 3 + 2];
    float my0 = mu_y[b * 3 + 0], my1 = mu_y[b * 3 + 1], my2 = mu_y[b * 3 + 2];
    const float* zx = g_Z + b * 1536;
    const float* zy = g_Z + (64 + b) * 1536;

    double a[11];
#pragma unroll
    for (int i = 0; i < 11; ++i) a[i] = 0.0;

    for (int c = tid; c < 512; c += 128) {
        float x0 = zx[c * 3 + 0] - mx0, x1 = zx[c * 3 + 1] - mx1, x2 = zx[c * 3 + 2] - mx2;
        float y0 = zy[c * 3 + 0] - my0, y1 = zy[c * 3 + 1] - my1, y2 = zy[c * 3 + 2] - my2;
        a[0] += (double)x0 * y0; a[1] += (double)x0 * y1; a[2] += (double)x0 * y2;
        a[3] += (double)x1 * y0; a[4] += (double)x1 * y1; a[5] += (double)x1 * y2;
        a[6] += (double)x2 * y0; a[7] += (double)x2 * y1; a[8] += (double)x2 * y2;
        a[9]  += (double)x0 * x0 + (double)x1 * x1 + (double)x2 * x2;
        a[10] += (double)y0 * y0 + (double)y1 * y1 + (double)y2 * y2;
    }
#pragma unroll
    for (int i = 0; i < 11; ++i)
        for (int off = 16; off > 0; off >>= 1)
            a[i] += __shfl_xor_sync(0xffffffffu, a[i], off);
    int warp = tid >> 5, lane = tid & 31;
    if (lane == 0)
        for (int i = 0; i < 11; ++i) smr[warp][i] = a[i];
    __syncthreads();

    if (tid == 0) {
        for (int i = 0; i < 11; ++i)
            a[i] = (smr[0][i] + smr[1][i]) + (smr[2][i] + smr[3][i]);
        double X[9];
        for (int i = 0; i < 9; ++i) X[i] = a[i];

        for (int it = 0; it < 9; ++it) {
            double C[9];
            C[0] = X[4] * X[8] - X[5] * X[7];
            C[1] = X[5] * X[6] - X[3] * X[8];
            C[2] = X[3] * X[7] - X[4] * X[6];
            C[3] = X[2] * X[7] - X[1] * X[8];
            C[4] = X[0] * X[8] - X[2] * X[6];
            C[5] = X[1] * X[6] - X[0] * X[7];
            C[6] = X[1] * X[5] - X[2] * X[4];
            C[7] = X[2] * X[3] - X[0] * X[5];
            C[8] = X[0] * X[4] - X[1] * X[3];
            double det = X[0] * C[0] + X[1] * C[1] + X[2] * C[2];
            double invdet = 1.0 / det;
            double mu = 1.0, inv_mu = 1.0;
            if (it < 4) {
                // tree-shaped Frobenius norms (shorter dependency chains)
                double fx2 = (((X[0]*X[0] + X[1]*X[1]) + (X[2]*X[2] + X[3]*X[3]))
                           +  ((X[4]*X[4] + X[5]*X[5]) + (X[6]*X[6] + X[7]*X[7]))) + X[8]*X[8];
                double fc2 = (((C[0]*C[0] + C[1]*C[1]) + (C[2]*C[2] + C[3]*C[3]))
                           +  ((C[4]*C[4] + C[5]*C[5]) + (C[6]*C[6] + C[7]*C[7]))) + C[8]*C[8];
                double fy2 = fc2 * invdet * invdet;   // ||X^{-1}||_F^2
                mu = sqrt(sqrt(fy2 / fx2));
                inv_mu = 1.0 / mu;
            }
#pragma unroll
            for (int i = 0; i < 9; ++i)
                X[i] = 0.5 * (mu * X[i] + inv_mu * C[i] * invdet);
        }

        for (int i = 0; i < 9; ++i) out[b * 9 + i] = (float)X[i];
        double t0 = (double)my0 - (X[0] * mx0 + X[1] * mx1 + X[2] * mx2);
        double t1 = (double)my1 - (X[3] * mx0 + X[4] * mx1 + X[5] * mx2);
        double t2 = (double)my2 - (X[6] * mx0 + X[7] * mx1 + X[8] * mx2);
        out[576 + b * 3 + 0] = (float)t0;
        out[576 + b * 3 + 1] = (float)t1;
        out[576 + b * 3 + 2] = (float)t2;
        double xn = sqrt(a[9]), yn = sqrt(a[10]);
        out[768 + b] = (float)(yn / (xn + 1e-6));
    }
}

// ---------------------------------------------------------------------------
extern "C" void kernel_launch(void* const* d_in, const int* in_sizes, int n_in,
                              void* d_out, int out_size) {
    int xi[4], yi[4];
    if (in_sizes[0] == in_sizes[1]) {
        for (int i = 0; i < 4; ++i) { xi[i] = 2 * i; yi[i] = 2 * i + 1; }
    } else {
        for (int i = 0; i < 4; ++i) { xi[i] = i; yi[i] = 4 + i; }
    }
    const float* mu_x = (const float*)d_in[8];
    const float* mu_y = (const float*)d_in[9];
    const float* W    = (const float*)d_in[10];
    const float* Wd   = (const float*)d_in[11];

    static const int chans[4] = {64, 128, 128, 192};
    static const int npts[4]  = {4096, 1024, 256, 64};
    static const int choff[4] = {0, 64, 192, 320};

    MeanArgs A;
    int wb = 0;
    for (int i = 0; i < 4; ++i) {
        for (int side = 0; side < 2; ++side) {
            int t = i * 2 + side;
            A.src[t]      = (const float*)d_in[side == 0 ? xi[i] : yi[i]];
            A.n4[t]       = npts[i] >> 2;
            A.inv_n[t]    = 1.0f / (float)npts[i];
            A.chan[t]     = chans[i];
            A.chan_off[t] = choff[i];
            A.bs_off[t]   = side == 0 ? 0 : 64;
            A.warp_base[t] = wb;
            int rows = 64 * chans[i] * 3;
            wb += (npts[i] == 64) ? rows / 2 : rows;
        }
    }
    A.warp_base[8] = wb;

    mean_fused_kernel<<<(wb + 7) / 8, 256>>>(A);
    vnmlp_kernel<<<dim3(16, 16), 256>>>(W, Wd);
    kabsch_kernel<<<64, 128>>>(mu_x, mu_y, (float*)d_out);
}

// round 5
// speedup vs baseline: 1.7883x; 1.1531x over previous
#include <cuda_runtime.h>

// Scratch (device globals — no allocation allowed).
// g_F: pooled means, layout [bs][512][3], bs 0..63 = x side, 64..127 = y side.
// g_Z: VN-MLP activated output, layout [bs][512][3].
static __device__ float g_F[128 * 512 * 3];
static __device__ float g_Z[128 * 512 * 3];

// ---------------------------------------------------------------------------
// Kernel 1 (fused): mean over point dim for ALL 8 tensors in one launch.
// One warp per row; n=64 rows pack 2 per warp. Shuffle-only reduce, __ldcs.
// ---------------------------------------------------------------------------
struct MeanArgs {
    const float* src[8];
    int   n4[8];
    float inv_n[8];
    int   chan[8];
    int   chan_off[8];
    int   bs_off[8];
    int   warp_base[9];
};

__global__ void __launch_bounds__(256) mean_fused_kernel(MeanArgs A) {
    int w = blockIdx.x * 8 + (threadIdx.x >> 5);
    int lane = threadIdx.x & 31;
    if (w >= A.warp_base[8]) return;

    int t = 0;
#pragma unroll
    for (int i = 1; i < 8; ++i) t += (w >= A.warp_base[i]) ? 1 : 0;
    int lw = w - A.warp_base[t];
    int n4 = A.n4[t];
    const float4* p = reinterpret_cast<const float4*>(A.src[t]);

    int row;
    float s = 0.f;
    bool writer;

    if (n4 >= 32) {
        row = lw;
        const float4* q = p + (long long)row * n4;
#pragma unroll 8
        for (int i = lane; i < n4; i += 32) {
            float4 v = __ldcs(q + i);
            s += (v.x + v.y) + (v.z + v.w);
        }
#pragma unroll
        for (int off = 16; off > 0; off >>= 1)
            s += __shfl_xor_sync(0xffffffffu, s, off);
        writer = (lane == 0);
    } else {
        row = lw * 2 + (lane >> 4);
        int sl = lane & 15;
        float4 v = __ldcs(p + (long long)row * 16 + sl);
        s = (v.x + v.y) + (v.z + v.w);
#pragma unroll
        for (int off = 8; off > 0; off >>= 1)
            s += __shfl_xor_sync(0xffffffffu, s, off);
        writer = (sl == 0);
    }

    if (writer) {
        int chan = A.chan[t];
        int d = row % 3;
        int c = (row / 3) % chan;
        int b = row / (3 * chan);
        g_F[((A.bs_off[t] + b) * 512 + (A.chan_off[t] + c)) * 3 + d] = s * A.inv_n[t];
    }
}

// ---------------------------------------------------------------------------
// Kernel 2: VN-MLP, packed f32x2 FMAs.
// Grid (32 o-tiles of 16, 16 bs-tiles of 8); warp = 2 outputs, lanes split K.
// Per-block W slice = 16 outputs x 512 x 2 mats x 4B = 64KB -> stays L1-hot
// across the 8 bs passes (L1 = 228KB - 48KB smem). F tile transposed in smem.
// ---------------------------------------------------------------------------
union F4U { float4 f4; unsigned long long u[2]; float f[4]; };

__device__ __forceinline__ void ffma2(unsigned long long& d,
                                      unsigned long long a, unsigned long long b) {
    asm("fma.rn.f32x2 %0, %1, %2, %0;" : "+l"(d) : "l"(a), "l"(b));
}

__global__ void __launch_bounds__(256) vnmlp_kernel(const float* __restrict__ W,
                                                    const float* __restrict__ Wd) {
    __shared__ float Fs[8 * 1536];   // [bs][dim][512]
    int bs0 = blockIdx.y * 8;
    const float* src = g_F + bs0 * 1536;
    for (int i = threadIdx.x; i < 8 * 1536; i += 256) {
        int bs = i / 1536, r = i % 1536;
        Fs[bs * 1536 + (r % 3) * 512 + (r / 3)] = src[i];
    }
    __syncthreads();

    int warp = threadIdx.x >> 5, lane = threadIdx.x & 31;
    int o0 = blockIdx.x * 16 + warp * 2;

    for (int bs = 0; bs < 8; ++bs) {
        unsigned long long acc[2][6];
#pragma unroll
        for (int j = 0; j < 2; ++j)
#pragma unroll
            for (int v = 0; v < 6; ++v) acc[j][v] = 0ull;

        const float* Fb = Fs + bs * 1536;
#pragma unroll
        for (int step = 0; step < 4; ++step) {
            int idx = step * 32 + lane;
            F4U f0, f1, f2;
            f0.f4 = reinterpret_cast<const float4*>(Fb)[idx];
            f1.f4 = reinterpret_cast<const float4*>(Fb + 512)[idx];
            f2.f4 = reinterpret_cast<const float4*>(Fb + 1024)[idx];
#pragma unroll
            for (int j = 0; j < 2; ++j) {
                F4U w, wd;
                w.f4  = __ldg(reinterpret_cast<const float4*>(W  + (o0 + j) * 512) + idx);
                wd.f4 = __ldg(reinterpret_cast<const float4*>(Wd + (o0 + j) * 512) + idx);
#pragma unroll
                for (int h = 0; h < 2; ++h) {
                    ffma2(acc[j][0], w.u[h],  f0.u[h]);
                    ffma2(acc[j][1], w.u[h],  f1.u[h]);
                    ffma2(acc[j][2], w.u[h],  f2.u[h]);
                    ffma2(acc[j][3], wd.u[h], f0.u[h]);
                    ffma2(acc[j][4], wd.u[h], f1.u[h]);
                    ffma2(acc[j][5], wd.u[h], f2.u[h]);
                }
            }
        }

        float r[2][6];
#pragma unroll
        for (int j = 0; j < 2; ++j)
#pragma unroll
            for (int v = 0; v < 6; ++v) {
                unsigned int lo = (unsigned int)(acc[j][v] & 0xffffffffull);
                unsigned int hi = (unsigned int)(acc[j][v] >> 32);
                float s = __uint_as_float(lo) + __uint_as_float(hi);
#pragma unroll
                for (int off = 16; off > 0; off >>= 1)
                    s += __shfl_xor_sync(0xffffffffu, s, off);
                r[j][v] = s;
            }

        if (lane == 0) {
#pragma unroll
            for (int j = 0; j < 2; ++j) {
                float px = r[j][0], py = r[j][1], pz = r[j][2];
                float dx = r[j][3], dy = r[j][4], dz = r[j][5];
                float dot = px * dx + py * dy + pz * dz;
                float d2  = dx * dx + dy * dy + dz * dz;
                float coef = (dot >= 0.f) ? 0.f : 0.8f * dot / (d2 + 1e-6f);
                float* o = g_Z + ((bs0 + bs) * 512 + (o0 + j)) * 3;
                o[0] = px - coef * dx;
                o[1] = py - coef * dy;
                o[2] = pz - coef * dz;
            }
        }
    }
}

// ---------------------------------------------------------------------------
// Kernel 3: per-batch Kabsch. fp64 cov; polar factor via Newton:
// 4 Frobenius-scaled + 2 plain iterations in fp32 (MUFU-speed div/sqrt),
// then 2 fp64 polish iterations. All iterates share the same polar factor,
// so fp32 only perturbs at ~1e-6*cond, far under the 1e-3 gate.
// ---------------------------------------------------------------------------
__global__ void kabsch_kernel(const float* __restrict__ mu_x,
                              const float* __restrict__ mu_y,
                              float* __restrict__ out) {
    __shared__ double smr[4][11];
    int b = blockIdx.x;
    int tid = threadIdx.x;
    float mx0 = mu_x[b * 3 + 0], mx1 = mu_x[b * 3 + 1], mx2 = mu_x[b * 3 + 2];
    float my0 = mu_y[b * 3 + 0], my1 = mu_y[b * 3 + 1], my2 = mu_y[b * 3 + 2];
    const float* zx = g_Z + b * 1536;
    const float* zy = g_Z + (64 + b) * 1536;

    double a[11];
#pragma unroll
    for (int i = 0; i < 11; ++i) a[i] = 0.0;

    for (int c = tid; c < 512; c += 128) {
        float x0 = zx[c * 3 + 0] - mx0, x1 = zx[c * 3 + 1] - mx1, x2 = zx[c * 3 + 2] - mx2;
        float y0 = zy[c * 3 + 0] - my0, y1 = zy[c * 3 + 1] - my1, y2 = zy[c * 3 + 2] - my2;
        a[0] += (double)x0 * y0; a[1] += (double)x0 * y1; a[2] += (double)x0 * y2;
        a[3] += (double)x1 * y0; a[4] += (double)x1 * y1; a[5] += (double)x1 * y2;
        a[6] += (double)x2 * y0; a[7] += (double)x2 * y1; a[8] += (double)x2 * y2;
        a[9]  += (double)x0 * x0 + (double)x1 * x1 + (double)x2 * x2;
        a[10] += (double)y0 * y0 + (double)y1 * y1 + (double)y2 * y2;
    }
#pragma unroll
    for (int i = 0; i < 11; ++i)
        for (int off = 16; off > 0; off >>= 1)
            a[i] += __shfl_xor_sync(0xffffffffu, a[i], off);
    int warp = tid >> 5, lane = tid & 31;
    if (lane == 0)
        for (int i = 0; i < 11; ++i) smr[warp][i] = a[i];
    __syncthreads();

    if (tid == 0) {
        for (int i = 0; i < 11; ++i)
            a[i] = (smr[0][i] + smr[1][i]) + (smr[2][i] + smr[3][i]);

        // fp32 Newton polar iteration (4 scaled + 2 plain)
        float X[9];
        for (int i = 0; i < 9; ++i) X[i] = (float)a[i];
        for (int it = 0; it < 6; ++it) {
            float C[9];
            C[0] = X[4] * X[8] - X[5] * X[7];
            C[1] = X[5] * X[6] - X[3] * X[8];
            C[2] = X[3] * X[7] - X[4] * X[6];
            C[3] = X[2] * X[7] - X[1] * X[8];
            C[4] = X[0] * X[8] - X[2] * X[6];
            C[5] = X[1] * X[6] - X[0] * X[7];
            C[6] = X[1] * X[5] - X[2] * X[4];
            C[7] = X[2] * X[3] - X[0] * X[5];
            C[8] = X[0] * X[4] - X[1] * X[3];
            float det = X[0] * C[0] + X[1] * C[1] + X[2] * C[2];
            float invdet = 1.0f / det;
            float mu = 1.0f, inv_mu = 1.0f;
            if (it < 4) {
                float fx2 = (((X[0]*X[0] + X[1]*X[1]) + (X[2]*X[2] + X[3]*X[3]))
                          +  ((X[4]*X[4] + X[5]*X[5]) + (X[6]*X[6] + X[7]*X[7]))) + X[8]*X[8];
                float fc2 = (((C[0]*C[0] + C[1]*C[1]) + (C[2]*C[2] + C[3]*C[3]))
                          +  ((C[4]*C[4] + C[5]*C[5]) + (C[6]*C[6] + C[7]*C[7]))) + C[8]*C[8];
                float fy2 = fc2 * invdet * invdet;
                mu = sqrtf(sqrtf(fy2 / fx2));
                inv_mu = 1.0f / mu;
            }
#pragma unroll
            for (int i = 0; i < 9; ++i)
                X[i] = 0.5f * (mu * X[i] + inv_mu * C[i] * invdet);
        }

        // fp64 polish (2 plain Newton steps)
        double Y[9];
        for (int i = 0; i < 9; ++i) Y[i] = (double)X[i];
        for (int it = 0; it < 2; ++it) {
            double C[9];
            C[0] = Y[4] * Y[8] - Y[5] * Y[7];
            C[1] = Y[5] * Y[6] - Y[3] * Y[8];
            C[2] = Y[3] * Y[7] - Y[4] * Y[6];
            C[3] = Y[2] * Y[7] - Y[1] * Y[8];
            C[4] = Y[0] * Y[8] - Y[2] * Y[6];
            C[5] = Y[1] * Y[6] - Y[0] * Y[7];
            C[6] = Y[1] * Y[5] - Y[2] * Y[4];
            C[7] = Y[2] * Y[3] - Y[0] * Y[5];
            C[8] = Y[0] * Y[4] - Y[1] * Y[3];
            double det = Y[0] * C[0] + Y[1] * C[1] + Y[2] * C[2];
            double invdet = 1.0 / det;
#pragma unroll
            for (int i = 0; i < 9; ++i)
                Y[i] = 0.5 * (Y[i] + C[i] * invdet);
        }

        for (int i = 0; i < 9; ++i) out[b * 9 + i] = (float)Y[i];
        double t0 = (double)my0 - (Y[0] * mx0 + Y[1] * mx1 + Y[2] * mx2);
        double t1 = (double)my1 - (Y[3] * mx0 + Y[4] * mx1 + Y[5] * mx2);
        double t2 = (double)my2 - (Y[6] * mx0 + Y[7] * mx1 + Y[8] * mx2);
        out[576 + b * 3 + 0] = (float)t0;
        out[576 + b * 3 + 1] = (float)t1;
        out[576 + b * 3 + 2] = (float)t2;
        double xn = sqrt(a[9]), yn = sqrt(a[10]);
        out[768 + b] = (float)(yn / (xn + 1e-6));
    }
}

// ---------------------------------------------------------------------------
extern "C" void kernel_launch(void* const* d_in, const int* in_sizes, int n_in,
                              void* d_out, int out_size) {
    int xi[4], yi[4];
    if (in_sizes[0] == in_sizes[1]) {
        for (int i = 0; i < 4; ++i) { xi[i] = 2 * i; yi[i] = 2 * i + 1; }
    } else {
        for (int i = 0; i < 4; ++i) { xi[i] = i; yi[i] = 4 + i; }
    }
    const float* mu_x = (const float*)d_in[8];
    const float* mu_y = (const float*)d_in[9];
    const float* W    = (const float*)d_in[10];
    const float* Wd   = (const float*)d_in[11];

    static const int chans[4] = {64, 128, 128, 192};
    static const int npts[4]  = {4096, 1024, 256, 64};
    static const int choff[4] = {0, 64, 192, 320};

    MeanArgs A;
    int wb = 0;
    for (int i = 0; i < 4; ++i) {
        for (int side = 0; side < 2; ++side) {
            int t = i * 2 + side;
            A.src[t]      = (const float*)d_in[side == 0 ? xi[i] : yi[i]];
            A.n4[t]       = npts[i] >> 2;
            A.inv_n[t]    = 1.0f / (float)npts[i];
            A.chan[t]     = chans[i];
            A.chan_off[t] = choff[i];
            A.bs_off[t]   = side == 0 ? 0 : 64;
            A.warp_base[t] = wb;
            int rows = 64 * chans[i] * 3;
            wb += (npts[i] == 64) ? rows / 2 : rows;
        }
    }
    A.warp_base[8] = wb;

    mean_fused_kernel<<<(wb + 7) / 8, 256>>>(A);
    vnmlp_kernel<<<dim3(32, 16), 256>>>(W, Wd);
    kabsch_kernel<<<64, 128>>>(mu_x, mu_y, (float*)d_out);
}